// round 3
// baseline (speedup 1.0000x reference)
#include <cuda_runtime.h>
#include <math_constants.h>

#define N_NODES 50000
#define N_EDGES 800000
#define M_TOT   850000   // edges + self loops
#define D 128

#define SCAN_CHUNK 1024
#define SCAN_NBLK  ((N_NODES + SCAN_CHUNK - 1) / SCAN_CHUNK)   // 49

typedef unsigned long long u64;

// ---------------- scratch (device globals; no allocation allowed) ----------
__device__ float  g_sum[1];
__device__ int    g_tick;
__device__ int    g_deg[N_NODES + 1];
__device__ int    g_rowptr[N_NODES + 1];
__device__ int    g_cnt[N_NODES];
__device__ int    g_blk[SCAN_NBLK];
__device__ int    g_off[SCAN_NBLK];
__device__ int2   g_csr[M_TOT];           // {src, weight-as-int}
__device__ float4 g_x0[N_NODES * 32];
__device__ float4 g_xl[N_NODES * 32];
__device__ float4 g_xr[N_NODES * 32];
__device__ float4 g_x1[N_NODES * 32];

// ---------------- f32x2 helpers (FFMA2: PTX-only on sm_103a) ---------------
__device__ __forceinline__ u64 pk2(float a, float b) {
    u64 r; asm("mov.b64 %0,{%1,%2};" : "=l"(r) : "f"(a), "f"(b)); return r;
}
__device__ __forceinline__ void upk2(u64 v, float& a, float& b) {
    asm("mov.b64 {%0,%1},%2;" : "=f"(a), "=f"(b) : "l"(v));
}
__device__ __forceinline__ u64 ffma2(u64 a, u64 b, u64 c) {
    u64 d; asm("fma.rn.f32x2 %0,%1,%2,%3;" : "=l"(d) : "l"(a), "l"(b), "l"(c)); return d;
}

// ---------------- setup: deg init + x0 gather + counter resets -------------
__global__ void setup_a_kernel(const int* __restrict__ node_ids,
                               const float* __restrict__ emb) {
    int i = blockIdx.x * blockDim.x + threadIdx.x;
    if (i < N_NODES * 32) {
        int node = i >> 5, c = i & 31;
        g_x0[i] = ((const float4*)emb)[node_ids[node] * 32 + c];
    }
    if (i <= N_NODES) g_deg[i] = (i < N_NODES) ? 1 : 0;   // +1 = self loop
    if (i == 0) { g_sum[0] = 0.f; g_tick = 0; }
}

// fused: histogram of dst + sum of edge weights
__global__ void hist_sumw_kernel(const int* __restrict__ ei, const float* __restrict__ ew) {
    int i = blockIdx.x * blockDim.x + threadIdx.x;
    float v = 0.f;
    if (i < N_EDGES) {
        atomicAdd(&g_deg[ei[N_EDGES + i]], 1);
        v = ew[i];
    }
    #pragma unroll
    for (int o = 16; o; o >>= 1) v += __shfl_xor_sync(0xffffffffu, v, o);
    if ((threadIdx.x & 31) == 0) atomicAdd(g_sum, v);
}

// ---- scan phase 1+2 fused: per-chunk sums, last block scans them ----------
__global__ void scan_pb_kernel() {
    __shared__ int ws[8];
    __shared__ int s_last;
    int b = blockIdx.x, tid = threadIdx.x;
    int base = b * SCAN_CHUNK + tid * 4;
    int s = 0;
    #pragma unroll
    for (int j = 0; j < 4; j++) {
        int idx = base + j;
        if (idx < N_NODES) s += g_deg[idx];
    }
    #pragma unroll
    for (int o = 16; o; o >>= 1) s += __shfl_xor_sync(0xffffffffu, s, o);
    if ((tid & 31) == 0) ws[tid >> 5] = s;
    __syncthreads();
    if (tid < 8) {
        int v = ws[tid];
        #pragma unroll
        for (int o = 4; o; o >>= 1) v += __shfl_xor_sync(0xffu, v, o);
        if (tid == 0) {
            g_blk[b] = v;
            __threadfence();
            int t = atomicAdd(&g_tick, 1);
            s_last = (t == SCAN_NBLK - 1);
        }
    }
    __syncthreads();
    if (!s_last || tid >= 32) return;
    // last-arriving block: exclusive scan of the 49 chunk sums (1 warp)
    int lane = tid;
    int v0 = (lane < SCAN_NBLK) ? g_blk[lane] : 0;
    int v1 = (lane + 32 < SCAN_NBLK) ? g_blk[lane + 32] : 0;
    int x = v0;
    #pragma unroll
    for (int o = 1; o < 32; o <<= 1) {
        int y = __shfl_up_sync(0xffffffffu, x, o);
        if (lane >= o) x += y;
    }
    int tot0 = __shfl_sync(0xffffffffu, x, 31);
    int z = v1;
    #pragma unroll
    for (int o = 1; o < 32; o <<= 1) {
        int y = __shfl_up_sync(0xffffffffu, z, o);
        if (lane >= o) z += y;
    }
    if (lane < SCAN_NBLK)      g_off[lane]      = x - v0;
    if (lane + 32 < SCAN_NBLK) g_off[lane + 32] = tot0 + z - v1;
}

// ---- scan phase 3: per-chunk exclusive scan + add block offset ------------
__global__ void scan_final_kernel() {
    __shared__ int ws[8];
    int b = blockIdx.x, tid = threadIdx.x;
    int lane = tid & 31, wid = tid >> 5;
    int base = b * SCAN_CHUNK + tid * 4;
    int d0 = 0, d1 = 0, d2 = 0, d3 = 0;
    if (base + 0 < N_NODES) d0 = g_deg[base + 0];
    if (base + 1 < N_NODES) d1 = g_deg[base + 1];
    if (base + 2 < N_NODES) d2 = g_deg[base + 2];
    if (base + 3 < N_NODES) d3 = g_deg[base + 3];
    int tsum = d0 + d1 + d2 + d3;
    int x = tsum;
    #pragma unroll
    for (int o = 1; o < 32; o <<= 1) {
        int y = __shfl_up_sync(0xffffffffu, x, o);
        if (lane >= o) x += y;
    }
    if (lane == 31) ws[wid] = x;
    __syncthreads();
    if (tid < 8) {
        int w = ws[tid];
        #pragma unroll
        for (int o = 1; o < 8; o <<= 1) {
            int y = __shfl_up_sync(0xffu, w, o);
            if (tid >= o) w += y;
        }
        ws[tid] = w;
    }
    __syncthreads();
    int woff = (wid > 0) ? ws[wid - 1] : 0;
    int excl = g_off[b] + woff + (x - tsum);
    int e0 = excl, e1 = e0 + d0, e2 = e1 + d1, e3 = e2 + d2;
    if (base + 0 < N_NODES) { g_rowptr[base + 0] = e0; g_cnt[base + 0] = e0; }
    if (base + 1 < N_NODES) { g_rowptr[base + 1] = e1; g_cnt[base + 1] = e1; }
    if (base + 2 < N_NODES) { g_rowptr[base + 2] = e2; g_cnt[base + 2] = e2; }
    if (base + 3 < N_NODES) { g_rowptr[base + 3] = e3; g_cnt[base + 3] = e3; }
    if (b == 0 && tid == 0) g_rowptr[N_NODES] = M_TOT;
}

__global__ void scatter_kernel(const int* __restrict__ ei, const float* __restrict__ ew) {
    int i = blockIdx.x * blockDim.x + threadIdx.x;
    if (i >= M_TOT) return;
    int s, d; float w;
    if (i < N_EDGES) { s = ei[i]; d = ei[N_EDGES + i]; w = ew[i]; }
    else             { s = d = i - N_EDGES; w = g_sum[0] * (1.0f / N_EDGES); }
    int pos = atomicAdd(&g_cnt[d], 1);
    g_csr[pos] = make_int2(s, __float_as_int(w));
}

// ---------------- GEMM: Y[M,128] = X[M,128] @ W[128,128] + B ---------------
__global__ __launch_bounds__(256) void gemm2_kernel(
    const float* __restrict__ X,
    const float* __restrict__ Wl, const float* __restrict__ Bl, float* __restrict__ Yl,
    const float* __restrict__ Wr, const float* __restrict__ Br, float* __restrict__ Yr)
{
    const float* W = (blockIdx.y == 0) ? Wl : Wr;
    const float* B = (blockIdx.y == 0) ? Bl : Br;
    float*       Y = (blockIdx.y == 0) ? Yl : Yr;

    __shared__ float2 xs[32 * 128];           // [row_pair][k]
    const int tx = threadIdx.x, ty = threadIdx.y;
    const int t  = ty * 32 + tx;
    const int r0 = blockIdx.x * 64;

    #pragma unroll
    for (int i = 0; i < 4; i++) {
        int u  = t + 256 * i;                 // 0..1023
        int rp = u >> 5, c4 = u & 31;
        int ra = r0 + 2 * rp, rb = ra + 1;
        float4 a = (ra < N_NODES) ? *(const float4*)(X + ra * D + c4 * 4) : make_float4(0,0,0,0);
        float4 b = (rb < N_NODES) ? *(const float4*)(X + rb * D + c4 * 4) : make_float4(0,0,0,0);
        xs[rp * 128 + 4 * c4 + 0] = make_float2(a.x, b.x);
        xs[rp * 128 + 4 * c4 + 1] = make_float2(a.y, b.y);
        xs[rp * 128 + 4 * c4 + 2] = make_float2(a.z, b.z);
        xs[rp * 128 + 4 * c4 + 3] = make_float2(a.w, b.w);
    }
    __syncthreads();

    u64 acc[4][4];
    #pragma unroll
    for (int j = 0; j < 4; j++)
        #pragma unroll
        for (int c = 0; c < 4; c++) acc[j][c] = 0ull;

    const float4* W4 = (const float4*)W;
    #pragma unroll 4
    for (int k = 0; k < D; k += 2) {
        float4 wA = W4[k * 32 + tx];
        float4 wB = W4[(k + 1) * 32 + tx];
        u64 wA0 = pk2(wA.x, wA.x), wA1 = pk2(wA.y, wA.y);
        u64 wA2 = pk2(wA.z, wA.z), wA3 = pk2(wA.w, wA.w);
        u64 wB0 = pk2(wB.x, wB.x), wB1 = pk2(wB.y, wB.y);
        u64 wB2 = pk2(wB.z, wB.z), wB3 = pk2(wB.w, wB.w);
        #pragma unroll
        for (int j = 0; j < 4; j++) {
            float4 xv = *(const float4*)&xs[(ty * 4 + j) * 128 + k];
            u64 x0 = pk2(xv.x, xv.y);   // (row_e, row_o) at k
            u64 x1 = pk2(xv.z, xv.w);   // (row_e, row_o) at k+1
            acc[j][0] = ffma2(x0, wA0, acc[j][0]);
            acc[j][1] = ffma2(x0, wA1, acc[j][1]);
            acc[j][2] = ffma2(x0, wA2, acc[j][2]);
            acc[j][3] = ffma2(x0, wA3, acc[j][3]);
            acc[j][0] = ffma2(x1, wB0, acc[j][0]);
            acc[j][1] = ffma2(x1, wB1, acc[j][1]);
            acc[j][2] = ffma2(x1, wB2, acc[j][2]);
            acc[j][3] = ffma2(x1, wB3, acc[j][3]);
        }
    }

    float4 b4 = *(const float4*)(B + tx * 4);
    #pragma unroll
    for (int j = 0; j < 4; j++) {
        int rp = ty * 4 + j;
        int ra = r0 + 2 * rp, rb = ra + 1;
        float e0,o0,e1,o1,e2,o2,e3,o3;
        upk2(acc[j][0], e0, o0); upk2(acc[j][1], e1, o1);
        upk2(acc[j][2], e2, o2); upk2(acc[j][3], e3, o3);
        if (ra < N_NODES)
            *(float4*)(Y + ra * D + tx * 4) = make_float4(e0 + b4.x, e1 + b4.y, e2 + b4.z, e3 + b4.w);
        if (rb < N_NODES)
            *(float4*)(Y + rb * D + tx * 4) = make_float4(o0 + b4.x, o1 + b4.y, o2 + b4.z, o3 + b4.w);
    }
}

// ---------------- fused attention + aggregate + residual + LN --------------
// one warp per dst node; DUAL-stream online softmax: the edge list is split
// in half and two independent (m,s,acc) states run interleaved, doubling ILP
// on the serial shfl-reduce/exp/rescale chain. States merged at the end.
#define NEG_BIG (-1e30f)

__device__ __forceinline__ float warp_sum(float l) {
    l += __shfl_xor_sync(0xffffffffu, l, 16);
    l += __shfl_xor_sync(0xffffffffu, l, 8);
    l += __shfl_xor_sync(0xffffffffu, l, 4);
    l += __shfl_xor_sync(0xffffffffu, l, 2);
    l += __shfl_xor_sync(0xffffffffu, l, 1);
    return l;
}

__global__ __launch_bounds__(256) void attn_kernel(
    const float* __restrict__ xl, const float* __restrict__ xr,
    const float* __restrict__ We, const float* __restrict__ att,
    const float* __restrict__ bias, const float* __restrict__ gam,
    const float* __restrict__ bet, const float* __restrict__ resid,
    float* __restrict__ out)
{
    int gw   = (blockIdx.x * blockDim.x + threadIdx.x) >> 5;
    int lane = threadIdx.x & 31;
    if (gw >= N_NODES) return;
    int c = lane * 4;

    float4 xr4 = *(const float4*)(xr + gw * D + c);
    float4 We4 = *(const float4*)(We + c);
    float4 at4 = *(const float4*)(att + c);

    int beg = g_rowptr[gw], end = g_rowptr[gw + 1];   // end > beg (self loop)
    int half = (end - beg + 1) >> 1;

    float m1 = NEG_BIG, s1 = 0.f, a1x = 0.f, a1y = 0.f, a1z = 0.f, a1w = 0.f;
    float m2 = NEG_BIG, s2 = 0.f, a2x = 0.f, a2y = 0.f, a2z = 0.f, a2w = 0.f;

    for (int t = 0; t < half; t++) {
        int iA = beg + t;
        int iB = beg + half + t;
        bool vB = (iB < end);
        int2 eA = g_csr[iA];
        int2 eB = g_csr[vB ? iB : iA];
        float wA = __int_as_float(eA.y);
        float wB = __int_as_float(eB.y);
        float4 xA = *(const float4*)(xl + eA.x * D + c);
        float4 xB = *(const float4*)(xl + eB.x * D + c);

        float p0 = xA.x + xr4.x + wA * We4.x; p0 = fmaxf(p0, 0.2f * p0);
        float p1 = xA.y + xr4.y + wA * We4.y; p1 = fmaxf(p1, 0.2f * p1);
        float p2 = xA.z + xr4.z + wA * We4.z; p2 = fmaxf(p2, 0.2f * p2);
        float p3 = xA.w + xr4.w + wA * We4.w; p3 = fmaxf(p3, 0.2f * p3);
        float q0 = xB.x + xr4.x + wB * We4.x; q0 = fmaxf(q0, 0.2f * q0);
        float q1 = xB.y + xr4.y + wB * We4.y; q1 = fmaxf(q1, 0.2f * q1);
        float q2 = xB.z + xr4.z + wB * We4.z; q2 = fmaxf(q2, 0.2f * q2);
        float q3 = xB.w + xr4.w + wB * We4.w; q3 = fmaxf(q3, 0.2f * q3);

        float lA = warp_sum(p0 * at4.x + p1 * at4.y + p2 * at4.z + p3 * at4.w);
        float lB = warp_sum(q0 * at4.x + q1 * at4.y + q2 * at4.z + q3 * at4.w);

        // stream A update
        float nm1 = fmaxf(m1, lA);
        float cs1 = __expf(m1 - nm1);
        float e1  = __expf(lA - nm1);
        s1  = s1  * cs1 + e1;
        a1x = a1x * cs1 + e1 * xA.x;
        a1y = a1y * cs1 + e1 * xA.y;
        a1z = a1z * cs1 + e1 * xA.z;
        a1w = a1w * cs1 + e1 * xA.w;
        m1 = nm1;

        // stream B update (zeroed when tail-invalid)
        lB = vB ? lB : NEG_BIG;
        float nm2 = fmaxf(m2, lB);
        float cs2 = __expf(m2 - nm2);
        float e2  = vB ? __expf(lB - nm2) : 0.f;
        s2  = s2  * cs2 + e2;
        a2x = a2x * cs2 + e2 * xB.x;
        a2y = a2y * cs2 + e2 * xB.y;
        a2z = a2z * cs2 + e2 * xB.z;
        a2w = a2w * cs2 + e2 * xB.w;
        m2 = nm2;
    }

    // merge the two online-softmax states
    float M  = fmaxf(m1, m2);
    float c1 = __expf(m1 - M);
    float c2 = __expf(m2 - M);
    float s  = s1 * c1 + s2 * c2;
    float ax = a1x * c1 + a2x * c2;
    float ay = a1y * c1 + a2y * c2;
    float az = a1z * c1 + a2z * c2;
    float aw = a1w * c1 + a2w * c2;

    float inv = 1.0f / s;
    float4 b4 = *(const float4*)(bias + c);
    float4 r4 = *(const float4*)(resid + gw * D + c);
    float hx = r4.x + ax * inv + b4.x;
    float hy = r4.y + ay * inv + b4.y;
    float hz = r4.z + az * inv + b4.z;
    float hw = r4.w + aw * inv + b4.w;

    float mu = warp_sum(hx + hy + hz + hw) * (1.0f / D);

    float dx = hx - mu, dy = hy - mu, dz = hz - mu, dw = hw - mu;
    float var = warp_sum(dx * dx + dy * dy + dz * dz + dw * dw) * (1.0f / D);
    float sc  = rsqrtf(var + 1e-5f);

    float4 g4  = *(const float4*)(gam + c);
    float4 be4 = *(const float4*)(bet + c);
    float4 o;
    o.x = dx * sc * g4.x + be4.x;
    o.y = dy * sc * g4.y + be4.y;
    o.z = dz * sc * g4.z + be4.z;
    o.w = dw * sc * g4.w + be4.w;
    *(float4*)(out + gw * D + c) = o;
}

// ---------------- host -----------------------------------------------------
extern "C" void kernel_launch(void* const* d_in, const int* in_sizes, int n_in,
                              void* d_out, int out_size)
{
    const int*   node_ids = (const int*)d_in[0];
    const int*   ei       = (const int*)d_in[1];
    const float* ew       = (const float*)d_in[2];
    const float* emb      = (const float*)d_in[3];
    const float* w1l = (const float*)d_in[4];
    const float* b1l = (const float*)d_in[5];
    const float* w1r = (const float*)d_in[6];
    const float* b1r = (const float*)d_in[7];
    const float* w1e = (const float*)d_in[8];
    const float* at1 = (const float*)d_in[9];
    const float* bi1 = (const float*)d_in[10];
    const float* g1  = (const float*)d_in[11];
    const float* be1 = (const float*)d_in[12];
    const float* w2l = (const float*)d_in[13];
    const float* b2l = (const float*)d_in[14];
    const float* w2r = (const float*)d_in[15];
    const float* b2r = (const float*)d_in[16];
    const float* w2e = (const float*)d_in[17];
    const float* at2 = (const float*)d_in[18];
    const float* bi2 = (const float*)d_in[19];
    const float* g2  = (const float*)d_in[20];
    const float* be2 = (const float*)d_in[21];
    float* out = (float*)d_out;

    float *x0, *xl, *xr, *x1;
    cudaGetSymbolAddress((void**)&x0, g_x0);
    cudaGetSymbolAddress((void**)&xl, g_xl);
    cudaGetSymbolAddress((void**)&xr, g_xr);
    cudaGetSymbolAddress((void**)&x1, g_x1);

    dim3 gb(32, 8);
    dim3 gemm_grid((N_NODES + 63) / 64, 2);      // 782 x 2
    const int AB = (N_NODES + 7) / 8;            // 6250 (8 warps/block)

    // launches ordered so gemm2(L1) is #4 (the one ncu captures); it only
    // depends on setup_a's gather, not on the CSR build.
    setup_a_kernel<<<(N_NODES * 32 + 255) / 256, 256>>>(node_ids, emb);   // 1
    hist_sumw_kernel<<<(N_EDGES + 255) / 256, 256>>>(ei, ew);             // 2
    scan_pb_kernel<<<SCAN_NBLK, 256>>>();                                 // 3
    gemm2_kernel<<<gemm_grid, gb>>>(x0, w1l, b1l, xl, w1r, b1r, xr);      // 4 <- profiled
    scan_final_kernel<<<SCAN_NBLK, 256>>>();                              // 5
    scatter_kernel<<<(M_TOT + 255) / 256, 256>>>(ei, ew);                 // 6
    attn_kernel<<<AB, 256>>>(xl, xr, w1e, at1, bi1, g1, be1, x0, x1);     // 7
    gemm2_kernel<<<gemm_grid, gb>>>(x1, w2l, b2l, xl, w2r, b2r, xr);      // 8
    attn_kernel<<<AB, 256>>>(xl, xr, w2e, at2, bi2, g2, be2, x1, out);    // 9
}

// round 6
// speedup vs baseline: 1.2526x; 1.2526x over previous
#include <cuda_runtime.h>
#include <math_constants.h>
#include <cstdint>

#define N_NODES 50000
#define N_EDGES 800000
#define M_TOT   850000   // edges + self loops
#define D 128

#define SCAN_CHUNK 1024
#define SCAN_NBLK  ((N_NODES + SCAN_CHUNK - 1) / SCAN_CHUNK)   // 49

typedef unsigned long long u64;

// ---------------- scratch (device globals; no allocation allowed) ----------
__device__ float  g_sum[1];
__device__ int    g_tick;
__device__ int    g_deg[N_NODES + 1];
__device__ int    g_rowptr[N_NODES + 1];
__device__ int    g_cnt[N_NODES];
__device__ int    g_blk[SCAN_NBLK];
__device__ int    g_off[SCAN_NBLK];
__device__ int2   g_csr[M_TOT];                 // {src | vocab<<17, weight-as-int}
__device__ float  g_tl[128 * D];                // emb@W1l + b1l  (per-vocab table)
__device__ float  g_tr[128 * D];                // emb@W1r + b1r
__device__ float4 g_xl[N_NODES * 32];
__device__ float4 g_xr[N_NODES * 32];
__device__ float4 g_x1[N_NODES * 32];

// ---------------- f32x2 helpers (FFMA2: PTX-only on sm_103a) ---------------
__device__ __forceinline__ u64 pk2(float a, float b) {
    u64 r; asm("mov.b64 %0,{%1,%2};" : "=l"(r) : "f"(a), "f"(b)); return r;
}
__device__ __forceinline__ void upk2(u64 v, float& a, float& b) {
    asm("mov.b64 {%0,%1},%2;" : "=f"(a), "=f"(b) : "l"(v));
}
__device__ __forceinline__ u64 ffma2(u64 a, u64 b, u64 c) {
    u64 d; asm("fma.rn.f32x2 %0,%1,%2,%3;" : "=l"(d) : "l"(a), "l"(b), "l"(c)); return d;
}

// ---------------- setup: deg init + counter resets -------------------------
__global__ void setup_kernel() {
    int i = blockIdx.x * blockDim.x + threadIdx.x;
    if (i <= N_NODES) g_deg[i] = (i < N_NODES) ? 1 : 0;   // +1 = self loop
    if (i == 0) { g_sum[0] = 0.f; g_tick = 0; }
}

// fused: histogram of dst + sum of edge weights
__global__ void hist_sumw_kernel(const int* __restrict__ ei, const float* __restrict__ ew) {
    int i = blockIdx.x * blockDim.x + threadIdx.x;
    float v = 0.f;
    if (i < N_EDGES) {
        atomicAdd(&g_deg[ei[N_EDGES + i]], 1);
        v = ew[i];
    }
    #pragma unroll
    for (int o = 16; o; o >>= 1) v += __shfl_xor_sync(0xffffffffu, v, o);
    if ((threadIdx.x & 31) == 0) atomicAdd(g_sum, v);
}

// ---------------- layer-1 vocab tables: T = emb @ W + b --------------------
// grid (16, 2), block 256. Each block: 8 vocab rows x 128 cols of one table.
__global__ void table_kernel(const float* __restrict__ emb,
                             const float* __restrict__ Wl, const float* __restrict__ bl,
                             const float* __restrict__ Wr, const float* __restrict__ br)
{
    const float* W = blockIdx.y ? Wr : Wl;
    const float* B = blockIdx.y ? br : bl;
    float*       T = blockIdx.y ? g_tr : g_tl;
    __shared__ float es[8][D];
    int v0 = blockIdx.x * 8;
    int tid = threadIdx.x;
    ((float4*)&es[0][0])[tid] = ((const float4*)(emb + v0 * D))[tid];   // 256 f4 = 8 rows
    __syncthreads();
    int n = tid & 127, h = tid >> 7;
    float bn = B[n];
    #pragma unroll
    for (int j = 0; j < 4; j++) {
        int vr = h * 4 + j;
        float s = bn;
        #pragma unroll 8
        for (int k = 0; k < D; k++) s += es[vr][k] * W[k * D + n];
        T[(v0 + vr) * D + n] = s;
    }
}

// ---- scan phase 1+2 fused ----
__global__ void scan_pb_kernel() {
    __shared__ int ws[8];
    __shared__ int s_last;
    int b = blockIdx.x, tid = threadIdx.x;
    int base = b * SCAN_CHUNK + tid * 4;
    int s = 0;
    #pragma unroll
    for (int j = 0; j < 4; j++) {
        int idx = base + j;
        if (idx < N_NODES) s += g_deg[idx];
    }
    #pragma unroll
    for (int o = 16; o; o >>= 1) s += __shfl_xor_sync(0xffffffffu, s, o);
    if ((tid & 31) == 0) ws[tid >> 5] = s;
    __syncthreads();
    if (tid < 8) {
        int v = ws[tid];
        #pragma unroll
        for (int o = 4; o; o >>= 1) v += __shfl_xor_sync(0xffu, v, o);
        if (tid == 0) {
            g_blk[b] = v;
            __threadfence();
            int t = atomicAdd(&g_tick, 1);
            s_last = (t == SCAN_NBLK - 1);
        }
    }
    __syncthreads();
    if (!s_last || tid >= 32) return;
    int lane = tid;
    int v0 = (lane < SCAN_NBLK) ? g_blk[lane] : 0;
    int v1 = (lane + 32 < SCAN_NBLK) ? g_blk[lane + 32] : 0;
    int x = v0;
    #pragma unroll
    for (int o = 1; o < 32; o <<= 1) {
        int y = __shfl_up_sync(0xffffffffu, x, o);
        if (lane >= o) x += y;
    }
    int tot0 = __shfl_sync(0xffffffffu, x, 31);
    int z = v1;
    #pragma unroll
    for (int o = 1; o < 32; o <<= 1) {
        int y = __shfl_up_sync(0xffffffffu, z, o);
        if (lane >= o) z += y;
    }
    if (lane < SCAN_NBLK)      g_off[lane]      = x - v0;
    if (lane + 32 < SCAN_NBLK) g_off[lane + 32] = tot0 + z - v1;
}

// ---- scan phase 3 ----
__global__ void scan_final_kernel() {
    __shared__ int ws[8];
    int b = blockIdx.x, tid = threadIdx.x;
    int lane = tid & 31, wid = tid >> 5;
    int base = b * SCAN_CHUNK + tid * 4;
    int d0 = 0, d1 = 0, d2 = 0, d3 = 0;
    if (base + 0 < N_NODES) d0 = g_deg[base + 0];
    if (base + 1 < N_NODES) d1 = g_deg[base + 1];
    if (base + 2 < N_NODES) d2 = g_deg[base + 2];
    if (base + 3 < N_NODES) d3 = g_deg[base + 3];
    int tsum = d0 + d1 + d2 + d3;
    int x = tsum;
    #pragma unroll
    for (int o = 1; o < 32; o <<= 1) {
        int y = __shfl_up_sync(0xffffffffu, x, o);
        if (lane >= o) x += y;
    }
    if (lane == 31) ws[wid] = x;
    __syncthreads();
    if (tid < 8) {
        int w = ws[tid];
        #pragma unroll
        for (int o = 1; o < 8; o <<= 1) {
            int y = __shfl_up_sync(0xffu, w, o);
            if (tid >= o) w += y;
        }
        ws[tid] = w;
    }
    __syncthreads();
    int woff = (wid > 0) ? ws[wid - 1] : 0;
    int excl = g_off[b] + woff + (x - tsum);
    int e0 = excl, e1 = e0 + d0, e2 = e1 + d1, e3 = e2 + d2;
    if (base + 0 < N_NODES) { g_rowptr[base + 0] = e0; g_cnt[base + 0] = e0; }
    if (base + 1 < N_NODES) { g_rowptr[base + 1] = e1; g_cnt[base + 1] = e1; }
    if (base + 2 < N_NODES) { g_rowptr[base + 2] = e2; g_cnt[base + 2] = e2; }
    if (base + 3 < N_NODES) { g_rowptr[base + 3] = e3; g_cnt[base + 3] = e3; }
    if (b == 0 && tid == 0) g_rowptr[N_NODES] = M_TOT;
}

// packs src index (17 bits) + src vocab id (7 bits) into csr.x
__global__ void scatter_kernel(const int* __restrict__ ei, const float* __restrict__ ew,
                               const int* __restrict__ node_ids) {
    int i = blockIdx.x * blockDim.x + threadIdx.x;
    if (i >= M_TOT) return;
    int s, d; float w;
    if (i < N_EDGES) { s = ei[i]; d = ei[N_EDGES + i]; w = ew[i]; }
    else             { s = d = i - N_EDGES; w = g_sum[0] * (1.0f / N_EDGES); }
    int packed = s | (node_ids[s] << 17);
    int pos = atomicAdd(&g_cnt[d], 1);
    g_csr[pos] = make_int2(packed, __float_as_int(w));
}

// ---------------- GEMM (layer 2): Y = X @ W + B, FFMA2 --------------------
__global__ __launch_bounds__(256, 4) void gemm2_kernel(
    const float* __restrict__ X,
    const float* __restrict__ Wl, const float* __restrict__ Bl, float* __restrict__ Yl,
    const float* __restrict__ Wr, const float* __restrict__ Br, float* __restrict__ Yr)
{
    const float* W = (blockIdx.y == 0) ? Wl : Wr;
    const float* B = (blockIdx.y == 0) ? Bl : Br;
    float*       Y = (blockIdx.y == 0) ? Yl : Yr;

    __shared__ float2 xs[32 * 128];           // [row_pair][k]
    const int tx = threadIdx.x, ty = threadIdx.y;
    const int t  = ty * 32 + tx;
    const int r0 = blockIdx.x * 64;

    #pragma unroll
    for (int i = 0; i < 4; i++) {
        int u  = t + 256 * i;                 // 0..1023
        int rp = u >> 5, c4 = u & 31;
        int ra = r0 + 2 * rp, rb = ra + 1;
        float4 a = (ra < N_NODES) ? *(const float4*)(X + ra * D + c4 * 4) : make_float4(0,0,0,0);
        float4 b = (rb < N_NODES) ? *(const float4*)(X + rb * D + c4 * 4) : make_float4(0,0,0,0);
        xs[rp * 128 + 4 * c4 + 0] = make_float2(a.x, b.x);
        xs[rp * 128 + 4 * c4 + 1] = make_float2(a.y, b.y);
        xs[rp * 128 + 4 * c4 + 2] = make_float2(a.z, b.z);
        xs[rp * 128 + 4 * c4 + 3] = make_float2(a.w, b.w);
    }
    __syncthreads();

    u64 acc[4][4];
    #pragma unroll
    for (int j = 0; j < 4; j++)
        #pragma unroll
        for (int c = 0; c < 4; c++) acc[j][c] = 0ull;

    const float4* W4 = (const float4*)W;
    #pragma unroll 4
    for (int k = 0; k < D; k += 2) {
        float4 wA = W4[k * 32 + tx];
        float4 wB = W4[(k + 1) * 32 + tx];
        u64 wA0 = pk2(wA.x, wA.x), wA1 = pk2(wA.y, wA.y);
        u64 wA2 = pk2(wA.z, wA.z), wA3 = pk2(wA.w, wA.w);
        u64 wB0 = pk2(wB.x, wB.x), wB1 = pk2(wB.y, wB.y);
        u64 wB2 = pk2(wB.z, wB.z), wB3 = pk2(wB.w, wB.w);
        #pragma unroll
        for (int j = 0; j < 4; j++) {
            float4 xv = *(const float4*)&xs[(ty * 4 + j) * 128 + k];
            u64 x0 = pk2(xv.x, xv.y);   // (row_e, row_o) at k
            u64 x1 = pk2(xv.z, xv.w);   // (row_e, row_o) at k+1
            acc[j][0] = ffma2(x0, wA0, acc[j][0]);
            acc[j][1] = ffma2(x0, wA1, acc[j][1]);
            acc[j][2] = ffma2(x0, wA2, acc[j][2]);
            acc[j][3] = ffma2(x0, wA3, acc[j][3]);
            acc[j][0] = ffma2(x1, wB0, acc[j][0]);
            acc[j][1] = ffma2(x1, wB1, acc[j][1]);
            acc[j][2] = ffma2(x1, wB2, acc[j][2]);
            acc[j][3] = ffma2(x1, wB3, acc[j][3]);
        }
    }

    float4 b4 = *(const float4*)(B + tx * 4);
    #pragma unroll
    for (int j = 0; j < 4; j++) {
        int rp = ty * 4 + j;
        int ra = r0 + 2 * rp, rb = ra + 1;
        float e0,o0,e1,o1,e2,o2,e3,o3;
        upk2(acc[j][0], e0, o0); upk2(acc[j][1], e1, o1);
        upk2(acc[j][2], e2, o2); upk2(acc[j][3], e3, o3);
        if (ra < N_NODES)
            *(float4*)(Y + ra * D + tx * 4) = make_float4(e0 + b4.x, e1 + b4.y, e2 + b4.z, e3 + b4.w);
        if (rb < N_NODES)
            *(float4*)(Y + rb * D + tx * 4) = make_float4(o0 + b4.x, o1 + b4.y, o2 + b4.z, o3 + b4.w);
    }
}

// ---------------- attention common pieces ----------------------------------
__device__ __forceinline__ float warp_sum(float l) {
    l += __shfl_xor_sync(0xffffffffu, l, 16);
    l += __shfl_xor_sync(0xffffffffu, l, 8);
    l += __shfl_xor_sync(0xffffffffu, l, 4);
    l += __shfl_xor_sync(0xffffffffu, l, 2);
    l += __shfl_xor_sync(0xffffffffu, l, 1);
    return l;
}

// ---------------- layer-1 attention: xl/xr via 64KB vocab tables -----------
// one warp per dst node; online softmax; xl[src] = g_tl[vocab(src)] (L1-hot),
// xr[dst] = g_tr[vocab(dst)], residual = emb[vocab(dst)].
__global__ __launch_bounds__(256) void attn1_kernel(
    const int* __restrict__ node_ids, const float* __restrict__ emb,
    const float* __restrict__ We, const float* __restrict__ att,
    const float* __restrict__ bias, const float* __restrict__ gam,
    const float* __restrict__ bet, float* __restrict__ out)
{
    int gw   = (blockIdx.x * blockDim.x + threadIdx.x) >> 5;
    int lane = threadIdx.x & 31;
    if (gw >= N_NODES) return;
    int c = lane * 4;

    int vd = __ldg(node_ids + gw);
    float4 xr4 = *(const float4*)(g_tr + vd * D + c);
    float4 r4  = *(const float4*)(emb + vd * D + c);
    float4 We4 = *(const float4*)(We + c);
    float4 at4 = *(const float4*)(att + c);

    int beg = g_rowptr[gw], end = g_rowptr[gw + 1];
    float m = -CUDART_INF_F, s = 0.f;
    float ax = 0.f, ay = 0.f, az = 0.f, aw = 0.f;

    int2  e0 = g_csr[beg];
    float wc = __int_as_float(e0.y);
    float4 xv = *(const float4*)(g_tl + (e0.x >> 17) * D + c);

    for (int i = beg; i < end; i++) {
        int   ni  = (i + 1 < end) ? i + 1 : i;
        int2  ne  = g_csr[ni];
        float nw  = __int_as_float(ne.y);
        float4 nxv = *(const float4*)(g_tl + (ne.x >> 17) * D + c);

        float t0 = xv.x + xr4.x + wc * We4.x; t0 = fmaxf(t0, 0.2f * t0);
        float t1 = xv.y + xr4.y + wc * We4.y; t1 = fmaxf(t1, 0.2f * t1);
        float t2 = xv.z + xr4.z + wc * We4.z; t2 = fmaxf(t2, 0.2f * t2);
        float t3 = xv.w + xr4.w + wc * We4.w; t3 = fmaxf(t3, 0.2f * t3);
        float l = warp_sum(t0 * at4.x + t1 * at4.y + t2 * at4.z + t3 * at4.w);
        float nm = fmaxf(m, l);
        float cs = __expf(m - nm);
        float e  = __expf(l - nm);
        s  = s  * cs + e;
        ax = ax * cs + e * xv.x;
        ay = ay * cs + e * xv.y;
        az = az * cs + e * xv.z;
        aw = aw * cs + e * xv.w;
        m = nm;
        xv = nxv; wc = nw;
    }

    float inv = 1.0f / s;
    float4 b4 = *(const float4*)(bias + c);
    float hx = r4.x + ax * inv + b4.x;
    float hy = r4.y + ay * inv + b4.y;
    float hz = r4.z + az * inv + b4.z;
    float hw = r4.w + aw * inv + b4.w;

    float mu = warp_sum(hx + hy + hz + hw) * (1.0f / D);
    float dx = hx - mu, dy = hy - mu, dz = hz - mu, dw = hw - mu;
    float var = warp_sum(dx * dx + dy * dy + dz * dz + dw * dw) * (1.0f / D);
    float sc  = rsqrtf(var + 1e-5f);

    float4 g4  = *(const float4*)(gam + c);
    float4 be4 = *(const float4*)(bet + c);
    float4 o;
    o.x = dx * sc * g4.x + be4.x;
    o.y = dy * sc * g4.y + be4.y;
    o.z = dz * sc * g4.z + be4.z;
    o.w = dw * sc * g4.w + be4.w;
    *(float4*)(out + gw * D + c) = o;
}

// ---------------- layer-2 attention: per-node xl/xr (L2 gather) ------------
__global__ __launch_bounds__(256) void attn2_kernel(
    const float* __restrict__ xl, const float* __restrict__ xr,
    const float* __restrict__ We, const float* __restrict__ att,
    const float* __restrict__ bias, const float* __restrict__ gam,
    const float* __restrict__ bet, const float* __restrict__ resid,
    float* __restrict__ out)
{
    int gw   = (blockIdx.x * blockDim.x + threadIdx.x) >> 5;
    int lane = threadIdx.x & 31;
    if (gw >= N_NODES) return;
    int c = lane * 4;

    float4 xr4 = *(const float4*)(xr + gw * D + c);
    float4 We4 = *(const float4*)(We + c);
    float4 at4 = *(const float4*)(att + c);

    int beg = g_rowptr[gw], end = g_rowptr[gw + 1];
    float m = -CUDART_INF_F, s = 0.f;
    float ax = 0.f, ay = 0.f, az = 0.f, aw = 0.f;

    int2  e0 = g_csr[beg];
    float wc = __int_as_float(e0.y);
    float4 xv = *(const float4*)(xl + (e0.x & 0x1FFFF) * D + c);

    for (int i = beg; i < end; i++) {
        int   ni  = (i + 1 < end) ? i + 1 : i;
        int2  ne  = g_csr[ni];
        float nw  = __int_as_float(ne.y);
        float4 nxv = *(const float4*)(xl + (ne.x & 0x1FFFF) * D + c);

        float t0 = xv.x + xr4.x + wc * We4.x; t0 = fmaxf(t0, 0.2f * t0);
        float t1 = xv.y + xr4.y + wc * We4.y; t1 = fmaxf(t1, 0.2f * t1);
        float t2 = xv.z + xr4.z + wc * We4.z; t2 = fmaxf(t2, 0.2f * t2);
        float t3 = xv.w + xr4.w + wc * We4.w; t3 = fmaxf(t3, 0.2f * t3);
        float l = warp_sum(t0 * at4.x + t1 * at4.y + t2 * at4.z + t3 * at4.w);
        float nm = fmaxf(m, l);
        float cs = __expf(m - nm);
        float e  = __expf(l - nm);
        s  = s  * cs + e;
        ax = ax * cs + e * xv.x;
        ay = ay * cs + e * xv.y;
        az = az * cs + e * xv.z;
        aw = aw * cs + e * xv.w;
        m = nm;
        xv = nxv; wc = nw;
    }

    float inv = 1.0f / s;
    float4 b4 = *(const float4*)(bias + c);
    float4 r4 = *(const float4*)(resid + gw * D + c);
    float hx = r4.x + ax * inv + b4.x;
    float hy = r4.y + ay * inv + b4.y;
    float hz = r4.z + az * inv + b4.z;
    float hw = r4.w + aw * inv + b4.w;

    float mu = warp_sum(hx + hy + hz + hw) * (1.0f / D);
    float dx = hx - mu, dy = hy - mu, dz = hz - mu, dw = hw - mu;
    float var = warp_sum(dx * dx + dy * dy + dz * dz + dw * dw) * (1.0f / D);
    float sc  = rsqrtf(var + 1e-5f);

    float4 g4  = *(const float4*)(gam + c);
    float4 be4 = *(const float4*)(bet + c);
    float4 o;
    o.x = dx * sc * g4.x + be4.x;
    o.y = dy * sc * g4.y + be4.y;
    o.z = dz * sc * g4.z + be4.z;
    o.w = dw * sc * g4.w + be4.w;
    *(float4*)(out + gw * D + c) = o;
}

// ---------------- host -----------------------------------------------------
extern "C" void kernel_launch(void* const* d_in, const int* in_sizes, int n_in,
                              void* d_out, int out_size)
{
    const int*   node_ids = (const int*)d_in[0];
    const int*   ei       = (const int*)d_in[1];
    const float* ew       = (const float*)d_in[2];
    const float* emb      = (const float*)d_in[3];
    const float* w1l = (const float*)d_in[4];
    const float* b1l = (const float*)d_in[5];
    const float* w1r = (const float*)d_in[6];
    const float* b1r = (const float*)d_in[7];
    const float* w1e = (const float*)d_in[8];
    const float* at1 = (const float*)d_in[9];
    const float* bi1 = (const float*)d_in[10];
    const float* g1  = (const float*)d_in[11];
    const float* be1 = (const float*)d_in[12];
    const float* w2l = (const float*)d_in[13];
    const float* b2l = (const float*)d_in[14];
    const float* w2r = (const float*)d_in[15];
    const float* b2r = (const float*)d_in[16];
    const float* w2e = (const float*)d_in[17];
    const float* at2 = (const float*)d_in[18];
    const float* bi2 = (const float*)d_in[19];
    const float* g2  = (const float*)d_in[20];
    const float* be2 = (const float*)d_in[21];
    float* out = (float*)d_out;

    float *xl, *xr, *x1;
    cudaGetSymbolAddress((void**)&xl, g_xl);
    cudaGetSymbolAddress((void**)&xr, g_xr);
    cudaGetSymbolAddress((void**)&x1, g_x1);

    dim3 gb(32, 8);
    dim3 gemm_grid((N_NODES + 63) / 64, 2);      // 782 x 2
    dim3 tbl_grid(16, 2);
    const int AB = (N_NODES + 7) / 8;            // 6250 (8 warps/block)

    setup_kernel<<<(N_NODES + 256) / 256, 256>>>();                           // 1
    hist_sumw_kernel<<<(N_EDGES + 255) / 256, 256>>>(ei, ew);                 // 2
    table_kernel<<<tbl_grid, 256>>>(emb, w1l, b1l, w1r, b1r);                 // 3
    scan_pb_kernel<<<SCAN_NBLK, 256>>>();                                     // 4 <- profiled
    scan_final_kernel<<<SCAN_NBLK, 256>>>();                                  // 5
    scatter_kernel<<<(M_TOT + 255) / 256, 256>>>(ei, ew, node_ids);           // 6
    attn1_kernel<<<AB, 256>>>(node_ids, emb, w1e, at1, bi1, g1, be1, x1);     // 7
    gemm2_kernel<<<gemm_grid, gb>>>(x1, w2l, b2l, xl, w2r, b2r, xr);          // 8
    attn2_kernel<<<AB, 256>>>(xl, xr, w2e, at2, bi2, g2, be2, x1, out);       // 9
}